// round 1
// baseline (speedup 1.0000x reference)
#include <cuda_runtime.h>

#define B_ 16
#define C_ 4
#define L_ 4096
#define K_ 256
#define S_ 128
#define W_ (L_ - S_ + 1)   // 3969
#define WT 128
#define KT 64
#define EPS_ 1e-8f

// Scratch (no allocations allowed in kernel_launch)
__device__ float g_shpT[C_ * S_ * K_];   // normalized shapelets, [c][s][k]
__device__ float g_inv[B_ * C_ * W_];    // 1/||window||, [b][c][w]

// ---------------------------------------------------------------------------
// Zero the output (poisoned to 0xAA by harness). relu makes all results >= 0,
// so 0 is the correct identity for the max-reduction.
// ---------------------------------------------------------------------------
__global__ void k_init_out(float* __restrict__ out) {
    int i = blockIdx.x * blockDim.x + threadIdx.x;
    if (i < B_ * K_) out[i] = 0.f;
}

// ---------------------------------------------------------------------------
// Normalize shapelets and transpose to [c][s][k] for coalesced tile staging.
// One block per (c,k), 128 threads (= S).
// ---------------------------------------------------------------------------
__global__ void k_norm_shp(const float* __restrict__ shp) {
    int c = blockIdx.x >> 8;          // blockIdx.x = c*K + k, K=256
    int k = blockIdx.x & 255;
    int s = threadIdx.x;
    float v = shp[(c * K_ + k) * S_ + s];
    float sq = v * v;
#pragma unroll
    for (int o = 16; o > 0; o >>= 1) sq += __shfl_xor_sync(0xffffffffu, sq, o);
    __shared__ float wsum[4];
    if ((threadIdx.x & 31) == 0) wsum[threadIdx.x >> 5] = sq;
    __syncthreads();
    float tot = wsum[0] + wsum[1] + wsum[2] + wsum[3];
    float inv = 1.f / fmaxf(sqrtf(tot), EPS_);
    g_shpT[(c * S_ + s) * K_ + k] = v * inv;
}

// ---------------------------------------------------------------------------
// Sliding-window inverse norms: g_inv[b][c][w] = 1/max(||x[b,c,w:w+S]||, eps)
// grid (B*C, 16), 256 threads; each thread computes one window directly from
// a staged smem row chunk (conflict-free: consecutive threads, consecutive w).
// ---------------------------------------------------------------------------
__global__ void k_inv_norm(const float* __restrict__ x) {
    __shared__ float xs[256 + S_ - 1];   // 383
    int bc = blockIdx.x;
    int w0 = blockIdx.y * 256;
    int tid = threadIdx.x;
    for (int i = tid; i < 256 + S_ - 1; i += 256) {
        int g = w0 + i;
        xs[i] = (g < L_) ? x[bc * L_ + g] : 0.f;
    }
    __syncthreads();
    int w = w0 + tid;
    if (w < W_) {
        float sum = 0.f;
#pragma unroll 8
        for (int s = 0; s < S_; s++) {
            float t = xs[tid + s];
            sum += t * t;
        }
        g_inv[bc * W_ + w] = 1.f / fmaxf(sqrtf(sum), EPS_);
    }
}

// ---------------------------------------------------------------------------
// Main fused kernel: raw correlation (implicit im2col) + per-window scale +
// channel sum + relu + max-over-w, reduced via atomics.
// Block tile: 128 w  x 64 k. 256 threads = (tx:16) x (ty:16).
// Thread tile: 8 w (stride 16) x 4 k (stride 16)  -> conflict-free LDS.
// ---------------------------------------------------------------------------
__global__ void __launch_bounds__(256) k_main(const float* __restrict__ x,
                                              float* __restrict__ out) {
    __shared__ float xs[WT + S_];        // 256 floats (need 255)
    __shared__ float ss[S_][KT];         // 32 KB
    __shared__ float smax[KT];

    int tid = threadIdx.x;
    int tx = tid & 15;
    int ty = tid >> 4;
    int w0 = blockIdx.x * WT;
    int k0 = blockIdx.y * KT;
    int b  = blockIdx.z;

    float acc[8][4];
#pragma unroll
    for (int i = 0; i < 8; i++)
#pragma unroll
        for (int j = 0; j < 4; j++) acc[i][j] = 0.f;

    for (int c = 0; c < C_; c++) {
        __syncthreads();
        // stage x tile (WT + S - 1 = 255 floats)
        if (tid < WT + S_ - 1) {
            int g = w0 + tid;
            xs[tid] = (g < L_) ? x[(b * C_ + c) * L_ + g] : 0.f;
        }
        // stage shapelet tile [S][KT] (coalesced 64-float rows)
        const float* sp = g_shpT + c * S_ * K_ + k0;
#pragma unroll
        for (int e = 0; e < (S_ * KT) / 256; e++) {
            int idx = e * 256 + tid;
            ((float*)ss)[idx] = sp[(idx >> 6) * K_ + (idx & 63)];
        }
        __syncthreads();

        float racc[8][4];
#pragma unroll
        for (int i = 0; i < 8; i++)
#pragma unroll
            for (int j = 0; j < 4; j++) racc[i][j] = 0.f;

#pragma unroll 4
        for (int s = 0; s < S_; s++) {
            float xa[8], sb[4];
#pragma unroll
            for (int i = 0; i < 8; i++) xa[i] = xs[tx + 16 * i + s];
#pragma unroll
            for (int j = 0; j < 4; j++) sb[j] = ss[s][ty + 16 * j];
#pragma unroll
            for (int i = 0; i < 8; i++)
#pragma unroll
                for (int j = 0; j < 4; j++) racc[i][j] += xa[i] * sb[j];
        }

        // apply per-window inverse norm, accumulate into channel sum
#pragma unroll
        for (int i = 0; i < 8; i++) {
            int w = w0 + tx + 16 * i;
            float iv = (w < W_) ? g_inv[(b * C_ + c) * W_ + w] : 0.f;
#pragma unroll
            for (int j = 0; j < 4; j++) acc[i][j] += racc[i][j] * iv;
        }
    }

    // epilogue: relu + max over this block's w-tile, then global atomicMax.
    if (tid < KT) smax[tid] = 0.f;
    __syncthreads();
#pragma unroll
    for (int j = 0; j < 4; j++) {
        float m = acc[0][j];
#pragma unroll
        for (int i = 1; i < 8; i++) m = fmaxf(m, acc[i][j]);
        m = fmaxf(m * 0.25f, 0.f);   // (1/C) and relu; monotonic so max-first ok
        atomicMax((int*)&smax[ty + 16 * j], __float_as_int(m));
    }
    __syncthreads();
    if (tid < KT)
        atomicMax((int*)&out[b * K_ + k0 + tid], __float_as_int(smax[tid]));
}

// ---------------------------------------------------------------------------
extern "C" void kernel_launch(void* const* d_in, const int* in_sizes, int n_in,
                              void* d_out, int out_size) {
    const float* x   = (const float*)d_in[0];   // (16,4,4096)
    const float* shp = (const float*)d_in[1];   // (4,256,128)
    float* out = (float*)d_out;                 // (16,1,256)

    k_init_out<<<(B_ * K_ + 255) / 256, 256>>>(out);
    k_norm_shp<<<C_ * K_, S_>>>(shp);
    k_inv_norm<<<dim3(B_ * C_, (W_ + 255) / 256), 256>>>(x);
    k_main<<<dim3((W_ + WT - 1) / WT, K_ / KT, B_), 256>>>(x, out);
}

// round 2
// speedup vs baseline: 3.8632x; 3.8632x over previous
#include <cuda_runtime.h>
#include <cuda_fp16.h>
#include <stdint.h>

#define B_ 16
#define C_ 4
#define L_ 4096
#define K_ 256
#define S_ 128
#define W_ (L_ - S_ + 1)   // 3969
#define EPS_ 1e-8f

#define WT 128             // w per block
#define KT 128             // k per block

__device__ __align__(256) half g_shpH[C_ * K_ * S_];  // normalized shapelets [c][k][s]
__device__ float g_inv[B_ * C_ * W_];                 // 1/||window||

// ---------------------------------------------------------------------------
__global__ void k_init_out(float* __restrict__ out) {
    int i = blockIdx.x * blockDim.x + threadIdx.x;
    if (i < B_ * K_) out[i] = 0.f;
}

// ---------------------------------------------------------------------------
// Normalize shapelets -> half, keep native [c][k][s] layout.
__global__ void k_norm_shp(const float* __restrict__ shp) {
    int c = blockIdx.x >> 8;
    int k = blockIdx.x & 255;
    int s = threadIdx.x;
    float v = shp[(c * K_ + k) * S_ + s];
    float sq = v * v;
#pragma unroll
    for (int o = 16; o > 0; o >>= 1) sq += __shfl_xor_sync(0xffffffffu, sq, o);
    __shared__ float wsum[4];
    if ((threadIdx.x & 31) == 0) wsum[threadIdx.x >> 5] = sq;
    __syncthreads();
    float tot = wsum[0] + wsum[1] + wsum[2] + wsum[3];
    float inv = 1.f / fmaxf(sqrtf(tot), EPS_);
    g_shpH[(c * K_ + k) * S_ + s] = __float2half(v * inv);
}

// ---------------------------------------------------------------------------
__global__ void k_inv_norm(const float* __restrict__ x) {
    __shared__ float xs[256 + S_ - 1];
    int bc = blockIdx.x;
    int w0 = blockIdx.y * 256;
    int tid = threadIdx.x;
    for (int i = tid; i < 256 + S_ - 1; i += 256) {
        int g = w0 + i;
        xs[i] = (g < L_) ? x[bc * L_ + g] : 0.f;
    }
    __syncthreads();
    int w = w0 + tid;
    if (w < W_) {
        float sum = 0.f;
#pragma unroll 8
        for (int s = 0; s < S_; s++) { float t = xs[tid + s]; sum += t * t; }
        g_inv[bc * W_ + w] = 1.f / fmaxf(sqrtf(sum), EPS_);
    }
}

// ---------------------------------------------------------------------------
__device__ __forceinline__ void ldsm4(uint32_t (&r)[4], uint32_t addr) {
    asm volatile("ldmatrix.sync.aligned.m8n8.x4.shared.b16 {%0,%1,%2,%3}, [%4];"
                 : "=r"(r[0]), "=r"(r[1]), "=r"(r[2]), "=r"(r[3]) : "r"(addr));
}
__device__ __forceinline__ void mma16816(float (&d)[4], const uint32_t (&a)[4],
                                         uint32_t b0, uint32_t b1) {
    asm volatile("mma.sync.aligned.m16n8k16.row.col.f32.f16.f16.f32 "
                 "{%0,%1,%2,%3}, {%4,%5,%6,%7}, {%8,%9}, {%0,%1,%2,%3};"
                 : "+f"(d[0]), "+f"(d[1]), "+f"(d[2]), "+f"(d[3])
                 : "r"(a[0]), "r"(a[1]), "r"(a[2]), "r"(a[3]), "r"(b0), "r"(b1));
}

// ---------------------------------------------------------------------------
// Main: per (b, w-tile, k-tile). 8 warps, each 32w x 64k. fp16 MMA mainloop.
// A via sliding strip A0[v][j] = x[w0+v+j] (v: 0..254, j: 0..15), stride 48B.
// B via [k][s] swizzled tile. Per-channel inv fold, fused relu/max epilogue.
__global__ void __launch_bounds__(256, 1) k_main(const float* __restrict__ x,
                                                 float* __restrict__ out) {
    __shared__ half  A0[256 * 24];     // 12 KB, row stride 24 halves (48 B)
    __shared__ half  Bs[128 * 128];    // 32 KB, 256B rows, XOR-swizzled chunks
    __shared__ float xraw[256];        // raw x strip (255 used)
    __shared__ float invs[128];        // inv-norm for this w-tile
    __shared__ float smax[KT];

    const int tid  = threadIdx.x;
    const int lane = tid & 31, wid = tid >> 5;
    const int ww = wid & 3;            // 0..3 : w direction
    const int wk = wid >> 2;           // 0..1 : k direction (64 k each)
    const int w0 = blockIdx.x * WT, k0 = blockIdx.y * KT, b = blockIdx.z;

    if (tid < KT) smax[tid] = 0.f;

    const uint32_t sA = (uint32_t)__cvta_generic_to_shared(A0);
    const uint32_t sB = (uint32_t)__cvta_generic_to_shared(Bs);

    // ldmatrix lane address components
    const int l15 = lane & 15;
    const int lhi = lane >> 4;                       // A: chunk select (s +8)
    const uint32_t aBase = sA + (uint32_t)(ww * 32 + l15) * 48 + (lhi << 4);
    const int brow = wk * 64 + ((lane >> 4) & 1) * 8 + (lane & 7); // + p*16
    const int bhi  = (lane >> 3) & 1;

    float acc[2][8][4];
#pragma unroll
    for (int mi = 0; mi < 2; mi++)
#pragma unroll
        for (int ni = 0; ni < 8; ni++)
#pragma unroll
            for (int d = 0; d < 4; d++) acc[mi][ni][d] = 0.f;

    for (int c = 0; c < C_; c++) {
        __syncthreads();   // WAR on smem from previous iteration

        // ---- stage raw x strip + inv + B tile -------------------------------
        if (tid < 255) {
            int g = w0 + tid;
            xraw[tid] = (g < L_) ? x[(b * C_ + c) * L_ + g] : 0.f;
        }
        if (tid < 128) {
            int w = w0 + tid;
            invs[tid] = (w < W_) ? g_inv[(b * C_ + c) * W_ + w] : 0.f;
        }
        {
            const half* bg = g_shpH + (size_t)(c * K_ + k0) * S_;
#pragma unroll
            for (int j = 0; j < 8; j++) {
                int idx = tid + 256 * j;          // 0..2047
                int kk = idx >> 4, ci = idx & 15;
                uint4 u = *(const uint4*)(bg + kk * S_ + ci * 8);
                *(uint4*)((char*)Bs + kk * 256 + ((ci ^ (kk & 7)) << 4)) = u;
            }
        }
        __syncthreads();

        // ---- build half strip A0 from xraw ----------------------------------
        if (tid < 255) {
            int v = tid;
#pragma unroll
            for (int hi = 0; hi < 2; hi++) {
                float f0 = xraw[v + 8 * hi + 0], f1 = xraw[v + 8 * hi + 1];
                float f2 = xraw[v + 8 * hi + 2], f3 = xraw[v + 8 * hi + 3];
                float f4 = xraw[v + 8 * hi + 4], f5 = xraw[v + 8 * hi + 5];
                float f6 = xraw[v + 8 * hi + 6], f7 = xraw[v + 8 * hi + 7];
                half2 h0 = __floats2half2_rn(f0, f1);
                half2 h1 = __floats2half2_rn(f2, f3);
                half2 h2 = __floats2half2_rn(f4, f5);
                half2 h3 = __floats2half2_rn(f6, f7);
                uint4 u;
                u.x = *(uint32_t*)&h0; u.y = *(uint32_t*)&h1;
                u.z = *(uint32_t*)&h2; u.w = *(uint32_t*)&h3;
                *(uint4*)((char*)A0 + v * 48 + hi * 16) = u;
            }
        }
        __syncthreads();

        // ---- MMA mainloop: 8 k-steps of 16 s -------------------------------
        float racc[2][8][4];
#pragma unroll
        for (int mi = 0; mi < 2; mi++)
#pragma unroll
            for (int ni = 0; ni < 8; ni++)
#pragma unroll
                for (int d = 0; d < 4; d++) racc[mi][ni][d] = 0.f;

#pragma unroll
        for (int st = 0; st < 8; st++) {
            uint32_t a[2][4];
#pragma unroll
            for (int mi = 0; mi < 2; mi++)
                ldsm4(a[mi], aBase + (uint32_t)(st + mi) * 16 * 48);

            uint32_t bb[4][4];
#pragma unroll
            for (int p = 0; p < 4; p++) {
                int row = brow + p * 16;
                uint32_t ad = sB + row * 256 + (((2 * st + bhi) ^ (row & 7)) << 4);
                ldsm4(bb[p], ad);
            }
#pragma unroll
            for (int mi = 0; mi < 2; mi++)
#pragma unroll
                for (int p = 0; p < 4; p++) {
                    mma16816(racc[mi][2 * p + 0], a[mi], bb[p][0], bb[p][1]);
                    mma16816(racc[mi][2 * p + 1], a[mi], bb[p][2], bb[p][3]);
                }
        }

        // ---- fold per-channel window inverse norm ---------------------------
#pragma unroll
        for (int mi = 0; mi < 2; mi++) {
            int wl = ww * 32 + mi * 16 + (lane >> 2);
            float i0 = invs[wl];
            float i1 = invs[wl + 8];
#pragma unroll
            for (int ni = 0; ni < 8; ni++) {
                acc[mi][ni][0] += i0 * racc[mi][ni][0];
                acc[mi][ni][1] += i0 * racc[mi][ni][1];
                acc[mi][ni][2] += i1 * racc[mi][ni][2];
                acc[mi][ni][3] += i1 * racc[mi][ni][3];
            }
        }
    }

    // ---- epilogue: relu + max over w, reduce to out[b][k] -------------------
#pragma unroll
    for (int ni = 0; ni < 8; ni++) {
#pragma unroll
        for (int cc = 0; cc < 2; cc++) {
            float m = fmaxf(fmaxf(acc[0][ni][cc], acc[0][ni][cc + 2]),
                            fmaxf(acc[1][ni][cc], acc[1][ni][cc + 2]));
            m = fmaxf(m * 0.25f, 0.f);
            m = fmaxf(m, __shfl_xor_sync(0xffffffffu, m, 4));
            m = fmaxf(m, __shfl_xor_sync(0xffffffffu, m, 8));
            m = fmaxf(m, __shfl_xor_sync(0xffffffffu, m, 16));
            if (lane < 4)
                atomicMax((int*)&smax[wk * 64 + ni * 8 + 2 * lane + cc],
                          __float_as_int(m));
        }
    }
    __syncthreads();
    if (tid < KT)
        atomicMax((int*)&out[b * K_ + k0 + tid], __float_as_int(smax[tid]));
}

// ---------------------------------------------------------------------------
extern "C" void kernel_launch(void* const* d_in, const int* in_sizes, int n_in,
                              void* d_out, int out_size) {
    const float* x   = (const float*)d_in[0];   // (16,4,4096)
    const float* shp = (const float*)d_in[1];   // (4,256,128)
    float* out = (float*)d_out;                 // (16,1,256)

    k_init_out<<<(B_ * K_ + 255) / 256, 256>>>(out);
    k_norm_shp<<<C_ * K_, S_>>>(shp);
    k_inv_norm<<<dim3(B_ * C_, (W_ + 255) / 256), 256>>>(x);
    k_main<<<dim3((W_ + WT - 1) / WT, K_ / KT, B_), 256>>>(x, out);
}

// round 4
// speedup vs baseline: 7.6419x; 1.9781x over previous
#include <cuda_runtime.h>
#include <cuda_fp16.h>
#include <stdint.h>

#define B_ 16
#define C_ 4
#define L_ 4096
#define K_ 256
#define S_ 128
#define W_ (L_ - S_ + 1)   // 3969
#define EPS_ 1e-8f

#define WT 128             // w per block (MMA M)
#define KT 128             // k per block (MMA N)

// Shapelets normalized -> fp16, PRE-SWIZZLED per-(ktile,channel) 32KB tile
// in the 256B-row XOR-swizzled layout the mainloop's ldmatrix expects, so
// staging is a plain linear cp.async copy.
__device__ __align__(256) half g_shpB[C_ * K_ * S_];   // [2 ktiles][4 c][16K half]
__device__ float g_inv[B_ * C_ * W_];

// ---------------------------------------------------------------------------
__global__ void k_init_out(float* __restrict__ out) {
    int i = blockIdx.x * blockDim.x + threadIdx.x;
    if (i < B_ * K_) out[i] = 0.f;
}

// Normalize shapelets -> half, scatter into swizzled tile image.
__global__ void k_norm_shp(const float* __restrict__ shp) {
    int c = blockIdx.x >> 8;
    int k = blockIdx.x & 255;
    int s = threadIdx.x;
    float v = shp[(c * K_ + k) * S_ + s];
    float sq = v * v;
#pragma unroll
    for (int o = 16; o > 0; o >>= 1) sq += __shfl_xor_sync(0xffffffffu, sq, o);
    __shared__ float wsum[4];
    if ((threadIdx.x & 31) == 0) wsum[threadIdx.x >> 5] = sq;
    __syncthreads();
    float tot = wsum[0] + wsum[1] + wsum[2] + wsum[3];
    float inv = 1.f / fmaxf(sqrtf(tot), EPS_);
    int tile = (k >> 7) * C_ + c;
    int row = k & 127;
    uint32_t off = (uint32_t)row * 256u + ((((uint32_t)(s >> 3)) ^ (row & 7)) << 4)
                 + (uint32_t)(s & 7) * 2u;
    *(half*)((char*)g_shpB + (size_t)tile * 32768 + off) = __float2half(v * inv);
}

// Sliding-window inverse norms.
__global__ void k_inv_norm(const float* __restrict__ x) {
    __shared__ float xs[256 + S_ - 1];
    int bc = blockIdx.x;
    int w0 = blockIdx.y * 256;
    int tid = threadIdx.x;
    for (int i = tid; i < 256 + S_ - 1; i += 256) {
        int g = w0 + i;
        xs[i] = (g < L_) ? x[bc * L_ + g] : 0.f;
    }
    __syncthreads();
    int w = w0 + tid;
    if (w < W_) {
        float sum = 0.f;
#pragma unroll 8
        for (int s = 0; s < S_; s++) { float t = xs[tid + s]; sum += t * t; }
        g_inv[bc * W_ + w] = 1.f / fmaxf(sqrtf(sum), EPS_);
    }
}

// ---------------------------------------------------------------------------
__device__ __forceinline__ void ldsm4(uint32_t (&r)[4], uint32_t addr) {
    asm volatile("ldmatrix.sync.aligned.m8n8.x4.shared.b16 {%0,%1,%2,%3}, [%4];"
                 : "=r"(r[0]), "=r"(r[1]), "=r"(r[2]), "=r"(r[3]) : "r"(addr));
}
__device__ __forceinline__ void mma16816(float (&d)[4], const uint32_t (&a)[4],
                                         uint32_t b0, uint32_t b1) {
    asm volatile("mma.sync.aligned.m16n8k16.row.col.f32.f16.f16.f32 "
                 "{%0,%1,%2,%3}, {%4,%5,%6,%7}, {%8,%9}, {%0,%1,%2,%3};"
                 : "+f"(d[0]), "+f"(d[1]), "+f"(d[2]), "+f"(d[3])
                 : "r"(a[0]), "r"(a[1]), "r"(a[2]), "r"(a[3]), "r"(b0), "r"(b1));
}
__device__ __forceinline__ void cp16(uint32_t dst, const void* src) {
    asm volatile("cp.async.cg.shared.global [%0], [%1], 16;"
                 :: "r"(dst), "l"(src) : "memory");
}

// dynamic smem layout (bytes)
#define SM_A   0                   // 32768 : A tile (normalized windows)
#define SM_B   32768               // 2 x 32768 : B tiles (double buffer)
#define SM_XS  (32768 * 3)         // 1024 : raw x strip (255 floats)
#define SM_IV  (SM_XS + 1024)      // 512  : inv norms (128 floats)
#define SM_MAX (SM_IV + 512)       // 512  : per-k running max
#define SMEM_TOT (SM_MAX + 512)

// ---------------------------------------------------------------------------
// Main: 8 warps, each 32w x 64k; fp16 MMA, f32 accumulate across channels.
// inv_norm folded into A; relu/max fused epilogue.
// ---------------------------------------------------------------------------
__global__ void __launch_bounds__(256, 2) k_main(const float* __restrict__ x,
                                                 float* __restrict__ out) {
    extern __shared__ char dsm[];
    half*  As   = (half*)(dsm + SM_A);
    float* xs   = (float*)(dsm + SM_XS);
    float* iv   = (float*)(dsm + SM_IV);
    float* smax = (float*)(dsm + SM_MAX);
    const uint32_t sA = (uint32_t)__cvta_generic_to_shared(dsm + SM_A);
    const uint32_t sB0 = (uint32_t)__cvta_generic_to_shared(dsm + SM_B);

    const int tid  = threadIdx.x;
    const int lane = tid & 31, wid = tid >> 5;
    const int ww = wid & 3;            // w direction (32 rows each)
    const int wk = wid >> 2;           // k direction (64 cols each)
    const int w0 = blockIdx.x * WT, k0 = blockIdx.y * KT, b = blockIdx.z;

    if (tid < KT) smax[tid] = 0.f;

    // ldmatrix lane address components
    const int l15 = lane & 15;
    const int lhi = lane >> 4;
    const uint32_t aRow = sA + (uint32_t)(ww * 32 + l15) * 256;
    const int aXor = l15 & 7;
    const int brow = wk * 64 + ((lane >> 4) & 1) * 8 + (lane & 7);   // + p*16
    const int bhi  = (lane >> 3) & 1;

    float acc[2][8][4];
#pragma unroll
    for (int mi = 0; mi < 2; mi++)
#pragma unroll
        for (int ni = 0; ni < 8; ni++)
#pragma unroll
            for (int d = 0; d < 4; d++) acc[mi][ni][d] = 0.f;

    // ---- initial loads: x strip / inv for c=0 (regs), cp.async B0 ----------
    float px = 0.f, piv = 0.f;
    if (tid < 255) { int g = w0 + tid; px = (g < L_) ? x[(b * C_) * L_ + g] : 0.f; }
    if (tid < 128) { int w = w0 + tid; piv = (w < W_) ? g_inv[(b * C_) * W_ + w] : 0.f; }
    {
        const char* src = (const char*)g_shpB + (size_t)(blockIdx.y * C_) * 32768;
#pragma unroll
        for (int j = 0; j < 8; j++) {
            int idx = tid + 256 * j;
            cp16(sB0 + idx * 16, src + idx * 16);
        }
        asm volatile("cp.async.commit_group;" ::: "memory");
    }
    if (tid < 255) xs[tid] = px;
    if (tid < 128) iv[tid] = piv;
    __syncthreads();

    for (int c = 0; c < C_; c++) {
        // ---- build A[w][s] = xs[w+s] * iv[w] (conflict-free LDS + STS) -----
        {
            int w = tid & 127, hf = tid >> 7;        // thread = half a w-row
            float s = iv[w];
            const float* xp = xs + w + hf * 64;
            char* rowp = (char*)As + w * 256;
            int swz = w & 7;
#pragma unroll
            for (int jj = 0; jj < 8; jj++) {
                int ci = hf * 8 + jj;
                const float* p = xp + jj * 8;
                half2 h0 = __floats2half2_rn(s * p[0], s * p[1]);
                half2 h1 = __floats2half2_rn(s * p[2], s * p[3]);
                half2 h2 = __floats2half2_rn(s * p[4], s * p[5]);
                half2 h3 = __floats2half2_rn(s * p[6], s * p[7]);
                uint4 u;
                u.x = *(uint32_t*)&h0; u.y = *(uint32_t*)&h1;
                u.z = *(uint32_t*)&h2; u.w = *(uint32_t*)&h3;
                *(uint4*)(rowp + ((ci ^ swz) << 4)) = u;
            }
        }
        // ---- prefetch next channel (regs) + cp.async next B tile -----------
        px = 0.f; piv = 0.f;
        if (c + 1 < C_) {
            if (tid < 255) {
                int g = w0 + tid;
                px = (g < L_) ? x[(b * C_ + c + 1) * L_ + g] : 0.f;
            }
            if (tid < 128) {
                int w = w0 + tid;
                piv = (w < W_) ? g_inv[(b * C_ + c + 1) * W_ + w] : 0.f;
            }
            const char* src = (const char*)g_shpB
                            + (size_t)(blockIdx.y * C_ + c + 1) * 32768;
            uint32_t dst = sB0 + ((c + 1) & 1) * 32768;
#pragma unroll
            for (int j = 0; j < 8; j++) {
                int idx = tid + 256 * j;
                cp16(dst + idx * 16, src + idx * 16);
            }
            asm volatile("cp.async.commit_group;" ::: "memory");
            asm volatile("cp.async.wait_group 1;" ::: "memory");
        } else {
            asm volatile("cp.async.wait_group 0;" ::: "memory");
        }
        __syncthreads();   // A built, B_c landed

        // ---- MMA mainloop: 8 s-steps of 16 --------------------------------
        const uint32_t sB = sB0 + (c & 1) * 32768;
#pragma unroll
        for (int st = 0; st < 8; st++) {
            uint32_t a[2][4];
#pragma unroll
            for (int mi = 0; mi < 2; mi++)
                ldsm4(a[mi], aRow + (uint32_t)mi * 4096
                             + (uint32_t)(((2 * st + lhi) ^ aXor) << 4));
            uint32_t bb[4][4];
#pragma unroll
            for (int p = 0; p < 4; p++) {
                int row = brow + p * 16;
                uint32_t ad = sB + row * 256 + (((2 * st + bhi) ^ (row & 7)) << 4);
                ldsm4(bb[p], ad);
            }
#pragma unroll
            for (int mi = 0; mi < 2; mi++)
#pragma unroll
                for (int p = 0; p < 4; p++) {
                    mma16816(acc[mi][2 * p + 0], a[mi], bb[p][0], bb[p][1]);
                    mma16816(acc[mi][2 * p + 1], a[mi], bb[p][2], bb[p][3]);
                }
        }
        __syncthreads();   // A/xs/iv free for next channel

        if (c + 1 < C_) {
            if (tid < 255) xs[tid] = px;
            if (tid < 128) iv[tid] = piv;
            __syncthreads();
        }
    }

    // ---- epilogue: relu + max over w, reduce to out[b][k] -------------------
#pragma unroll
    for (int ni = 0; ni < 8; ni++) {
#pragma unroll
        for (int cc = 0; cc < 2; cc++) {
            float m = fmaxf(fmaxf(acc[0][ni][cc], acc[0][ni][cc + 2]),
                            fmaxf(acc[1][ni][cc], acc[1][ni][cc + 2]));
            m = fmaxf(m * 0.25f, 0.f);
            m = fmaxf(m, __shfl_xor_sync(0xffffffffu, m, 4));
            m = fmaxf(m, __shfl_xor_sync(0xffffffffu, m, 8));
            m = fmaxf(m, __shfl_xor_sync(0xffffffffu, m, 16));
            if (lane < 4)
                atomicMax((int*)&smax[wk * 64 + ni * 8 + 2 * lane + cc],
                          __float_as_int(m));
        }
    }
    __syncthreads();
    if (tid < KT)
        atomicMax((int*)&out[b * K_ + k0 + tid], __float_as_int(smax[tid]));
}

// ---------------------------------------------------------------------------
extern "C" void kernel_launch(void* const* d_in, const int* in_sizes, int n_in,
                              void* d_out, int out_size) {
    const float* x   = (const float*)d_in[0];   // (16,4,4096)
    const float* shp = (const float*)d_in[1];   // (4,256,128)
    float* out = (float*)d_out;                 // (16,1,256)

    static int attr_done = 0;
    if (!attr_done) {
        cudaFuncSetAttribute(k_main, cudaFuncAttributeMaxDynamicSharedMemorySize,
                             SMEM_TOT);
        attr_done = 1;
    }

    k_init_out<<<(B_ * K_ + 255) / 256, 256>>>(out);
    k_norm_shp<<<C_ * K_, S_>>>(shp);
    k_inv_norm<<<dim3(B_ * C_, (W_ + 255) / 256), 256>>>(x);
    k_main<<<dim3((W_ + WT - 1) / WT, K_ / KT, B_), 256, SMEM_TOT>>>(x, out);
}